// round 3
// baseline (speedup 1.0000x reference)
#include <cuda_runtime.h>
#include <cuda_bf16.h>

// Gram-Schmidt over M=4 model outputs, per (batch, channel) vector of D=1024.
// x: [4, 128, 64, 1024] fp32, out same shape.
//
// R2: all 10 pairwise dots G_ij in ONE fused block reduction; GS coefficients
// are scalar algebra on G (lower-triangular T, basis_i = sum_j T_ij v_j).
// R3: software-pipeline TWO (b,c) pairs per CTA -- pair B's loads are issued
// before pair A's reduction critical path (butterfly + 2 barriers + finalize),
// and pair A's stores overlap pair B's reduction, so the DRAM pipe stays fed
// through the reduction bubbles.

#define NTHREADS 256
#define D_DIM 1024
#define NPAIRS 8192            // B*C
#define MSTRIDE 8388608LL      // B*C*D
#define NCTAS (NPAIRS / 2)

__device__ __forceinline__ float dot4(float4 a, float4 b) {
    return a.x * b.x + a.y * b.y + a.z * b.z + a.w * b.w;
}

// 10 pairwise dot partials + warp butterfly (packed u64 shuffles) + lane0 STS.
__device__ __forceinline__ void partials_reduce_sts(
    float4 v0, float4 v1, float4 v2, float4 v3,
    float (*red)[12], int lane, int warp)
{
    float p[10];
    p[0] = dot4(v0, v0); p[1] = dot4(v0, v1); p[2] = dot4(v0, v2);
    p[3] = dot4(v0, v3); p[4] = dot4(v1, v1); p[5] = dot4(v1, v2);
    p[6] = dot4(v1, v3); p[7] = dot4(v2, v2); p[8] = dot4(v2, v3);
    p[9] = dot4(v3, v3);

#pragma unroll
    for (int lvl = 16; lvl >= 1; lvl >>= 1) {
#pragma unroll
        for (int q = 0; q < 5; q++) {
            unsigned long long u =
                ((unsigned long long)__float_as_uint(p[2 * q + 1]) << 32) |
                (unsigned long long)__float_as_uint(p[2 * q]);
            unsigned long long r = __shfl_xor_sync(0xffffffffu, u, lvl);
            p[2 * q]     += __uint_as_float((unsigned)r);
            p[2 * q + 1] += __uint_as_float((unsigned)(r >> 32));
        }
    }

    if (lane == 0) {
        float4* row = reinterpret_cast<float4*>(red[warp]);
        row[0] = make_float4(p[0], p[1], p[2], p[3]);
        row[1] = make_float4(p[4], p[5], p[6], p[7]);
        red[warp][8] = p[8];
        red[warp][9] = p[9];
    }
}

// Scalar GS recurrence on the finished Gram matrix + 4 output stores.
__device__ __forceinline__ void finalize_store(
    const float* gsm,
    float4 v0, float4 v1, float4 v2, float4 v3,
    float* __restrict__ out, long long base)
{
    float4 ga = *reinterpret_cast<const float4*>(gsm);
    float4 gb = *reinterpret_cast<const float4*>(gsm + 4);
    const float g23 = gsm[8], g33 = gsm[9];
    const float g00 = ga.x, g01 = ga.y, g02 = ga.z, g03 = ga.w;
    const float g11 = gb.x, g12 = gb.y, g13 = gb.z, g22 = gb.w;

    const float inv0 = (g00 > 0.f) ? rsqrtf(g00) : 0.f;

    const float c0 = g01 * inv0;
    const float n1 = fmaxf(g11 - c0 * c0, 0.f);
    const float inv1 = (n1 > 0.f) ? rsqrtf(n1) : 0.f;
    const float T10 = -c0 * inv0 * inv1;
    const float T11 = inv1;

    const float d0 = g02 * inv0;
    const float d1 = T10 * g02 + T11 * g12;
    const float n2 = fmaxf(g22 - d0 * d0 - d1 * d1, 0.f);
    const float inv2 = (n2 > 0.f) ? rsqrtf(n2) : 0.f;
    const float T20 = inv2 * (-d0 * inv0 - d1 * T10);
    const float T21 = inv2 * (-d1 * T11);
    const float T22 = inv2;

    const float e0 = g03 * inv0;
    const float e1 = T10 * g03 + T11 * g13;
    const float e2 = T20 * g03 + T21 * g13 + T22 * g23;
    const float n3 = fmaxf(g33 - e0 * e0 - e1 * e1 - e2 * e2, 0.f);
    const float inv3 = (n3 > 0.f) ? rsqrtf(n3) : 0.f;
    const float T30 = inv3 * (-e0 * inv0 - e1 * T10 - e2 * T20);
    const float T31 = inv3 * (-e1 * T11 - e2 * T21);
    const float T32 = inv3 * (-e2 * T22);
    const float T33 = inv3;

    float4 o;
    o.x = inv0 * v0.x; o.y = inv0 * v0.y; o.z = inv0 * v0.z; o.w = inv0 * v0.w;
    *reinterpret_cast<float4*>(out + base) = o;

    o.x = T10 * v0.x + T11 * v1.x; o.y = T10 * v0.y + T11 * v1.y;
    o.z = T10 * v0.z + T11 * v1.z; o.w = T10 * v0.w + T11 * v1.w;
    *reinterpret_cast<float4*>(out + MSTRIDE + base) = o;

    o.x = T20 * v0.x + T21 * v1.x + T22 * v2.x;
    o.y = T20 * v0.y + T21 * v1.y + T22 * v2.y;
    o.z = T20 * v0.z + T21 * v1.z + T22 * v2.z;
    o.w = T20 * v0.w + T21 * v1.w + T22 * v2.w;
    *reinterpret_cast<float4*>(out + 2 * MSTRIDE + base) = o;

    o.x = T30 * v0.x + T31 * v1.x + T32 * v2.x + T33 * v3.x;
    o.y = T30 * v0.y + T31 * v1.y + T32 * v2.y + T33 * v3.y;
    o.z = T30 * v0.z + T31 * v1.z + T32 * v2.z + T33 * v3.z;
    o.w = T30 * v0.w + T31 * v1.w + T32 * v2.w + T33 * v3.w;
    *reinterpret_cast<float4*>(out + 3 * MSTRIDE + base) = o;
}

__global__ __launch_bounds__(NTHREADS)
void gram_schmidt_kernel(const float* __restrict__ x, float* __restrict__ out) {
    const int tid  = threadIdx.x;
    const int lane = tid & 31;
    const int warp = tid >> 5;

    __shared__ float red[8][12];
    __shared__ float gsm[10];

    const long long baseA = (long long)(blockIdx.x * 2) * D_DIM + (long long)tid * 4;
    const long long baseB = baseA + D_DIM;

    // ---- pair A loads ----
    float4 a0 = *reinterpret_cast<const float4*>(x + baseA);
    float4 a1 = *reinterpret_cast<const float4*>(x + MSTRIDE + baseA);
    float4 a2 = *reinterpret_cast<const float4*>(x + 2 * MSTRIDE + baseA);
    float4 a3 = *reinterpret_cast<const float4*>(x + 3 * MSTRIDE + baseA);

    // ---- pair B loads issued early: latency covered by A's reduction ----
    float4 b0 = *reinterpret_cast<const float4*>(x + baseB);
    float4 b1 = *reinterpret_cast<const float4*>(x + MSTRIDE + baseB);
    float4 b2 = *reinterpret_cast<const float4*>(x + 2 * MSTRIDE + baseB);
    float4 b3 = *reinterpret_cast<const float4*>(x + 3 * MSTRIDE + baseB);

    // ---- pair A reduction ----
    partials_reduce_sts(a0, a1, a2, a3, red, lane, warp);
    __syncthreads();
    if (tid < 10) {
        float s = 0.f;
#pragma unroll
        for (int w = 0; w < 8; w++) s += red[w][tid];
        gsm[tid] = s;
    }
    __syncthreads();

    // ---- pair A finalize + stores (overlaps pair B reduction below) ----
    finalize_store(gsm, a0, a1, a2, a3, out, baseA);

    // ---- pair B reduction (red/gsm reuse is safe: red was consumed before
    //      the 2nd barrier above; every thread read gsm[A] into registers in
    //      program order before arriving at the next barrier) ----
    partials_reduce_sts(b0, b1, b2, b3, red, lane, warp);
    __syncthreads();
    if (tid < 10) {
        float s = 0.f;
#pragma unroll
        for (int w = 0; w < 8; w++) s += red[w][tid];
        gsm[tid] = s;
    }
    __syncthreads();

    // ---- pair B finalize + stores ----
    finalize_store(gsm, b0, b1, b2, b3, out, baseB);
}

extern "C" void kernel_launch(void* const* d_in, const int* in_sizes, int n_in,
                              void* d_out, int out_size) {
    const float* x = (const float*)d_in[0];
    float* out = (float*)d_out;
    gram_schmidt_kernel<<<NCTAS, NTHREADS>>>(x, out);
}

// round 5
// speedup vs baseline: 1.0185x; 1.0185x over previous
#include <cuda_runtime.h>
#include <cuda_bf16.h>

// Gram-Schmidt over M=4 model outputs, per (batch, channel) vector of D=1024.
// x: [4, 128, 64, 1024] fp32, out same shape.
//
// R2: all 10 pairwise dots G_ij in ONE fused block reduction; GS coefficients
//     are scalar algebra on G (lower-triangular T, basis_i = sum_j T_ij v_j).
// R4/R5: register diet (32-bit byte-offset addressing, launch_bounds min 6
//     blocks/SM) to raise resident CTAs 5->6, + evict-first streaming hints
//     (__ldcs/__stcs) since no byte is ever reused.
//     (R5 = resubmit of R4: container infra failure, kernel never ran.)

#define NTHREADS 256
#define D_DIM 1024
#define NPAIRS 8192              // B*C
#define MSTRIDE_B 33554432u      // B*C*D*4 bytes = 32 MB

__device__ __forceinline__ float dot4(float4 a, float4 b) {
    return a.x * b.x + a.y * b.y + a.z * b.z + a.w * b.w;
}

__global__ __launch_bounds__(NTHREADS, 6)
void gram_schmidt_kernel(const float* __restrict__ x, float* __restrict__ out) {
    const int tid  = threadIdx.x;
    const int lane = tid & 31;
    const int warp = tid >> 5;

    __shared__ float red[8][12];             // per-warp partials (padded rows)
    __shared__ __align__(16) float gsm[12];  // final Gram entries

    // 32-bit byte offset: max = 8191*4096 + 255*16 + 3*32MB < 2^28, fits unsigned.
    const unsigned base = blockIdx.x * (D_DIM * 4u) + (unsigned)tid * 16u;
    const char* xb = (const char*)x;
    char* ob = (char*)out;

    // Coalesced LDG.128, evict-first (streaming) — data is never re-read.
    float4 v0 = __ldcs((const float4*)(xb + base));
    float4 v1 = __ldcs((const float4*)(xb + base + MSTRIDE_B));
    float4 v2 = __ldcs((const float4*)(xb + base + 2u * MSTRIDE_B));
    float4 v3 = __ldcs((const float4*)(xb + base + 3u * MSTRIDE_B));

    // 10 pairwise dot partials: (00)(01)(02)(03)(11)(12)(13)(22)(23)(33)
    float p[10];
    p[0] = dot4(v0, v0); p[1] = dot4(v0, v1); p[2] = dot4(v0, v2);
    p[3] = dot4(v0, v3); p[4] = dot4(v1, v1); p[5] = dot4(v1, v2);
    p[6] = dot4(v1, v3); p[7] = dot4(v2, v2); p[8] = dot4(v2, v3);
    p[9] = dot4(v3, v3);

    // Warp butterfly: 10 values packed as 5 x 64-bit shuffles per level.
#pragma unroll
    for (int lvl = 16; lvl >= 1; lvl >>= 1) {
#pragma unroll
        for (int q = 0; q < 5; q++) {
            unsigned long long u =
                ((unsigned long long)__float_as_uint(p[2 * q + 1]) << 32) |
                (unsigned long long)__float_as_uint(p[2 * q]);
            unsigned long long r = __shfl_xor_sync(0xffffffffu, u, lvl);
            p[2 * q]     += __uint_as_float((unsigned)r);
            p[2 * q + 1] += __uint_as_float((unsigned)(r >> 32));
        }
    }

    if (lane == 0) {
        float4* row = reinterpret_cast<float4*>(red[warp]);
        row[0] = make_float4(p[0], p[1], p[2], p[3]);
        row[1] = make_float4(p[4], p[5], p[6], p[7]);
        red[warp][8] = p[8];
        red[warp][9] = p[9];
    }
    __syncthreads();

    // 10 threads finalize across the 8 warps (stride-12 rows: conflict-free).
    if (tid < 10) {
        float s = 0.f;
#pragma unroll
        for (int w = 0; w < 8; w++) s += red[w][tid];
        gsm[tid] = s;
    }
    __syncthreads();

    // Broadcast-read final Gram.
    float4 ga = *reinterpret_cast<const float4*>(gsm);
    float4 gb = *reinterpret_cast<const float4*>(gsm + 4);
    const float g23 = gsm[8], g33 = gsm[9];
    const float g00 = ga.x, g01 = ga.y, g02 = ga.z, g03 = ga.w;
    const float g11 = gb.x, g12 = gb.y, g13 = gb.z, g22 = gb.w;

    // ---- scalar GS recurrence on the Gram matrix (replicated per thread) ----
    const float inv0 = (g00 > 0.f) ? rsqrtf(g00) : 0.f;

    const float c0 = g01 * inv0;
    const float n1 = fmaxf(g11 - c0 * c0, 0.f);
    const float inv1 = (n1 > 0.f) ? rsqrtf(n1) : 0.f;
    const float T10 = -c0 * inv0 * inv1;
    const float T11 = inv1;

    const float d0 = g02 * inv0;
    const float d1 = T10 * g02 + T11 * g12;
    const float n2 = fmaxf(g22 - d0 * d0 - d1 * d1, 0.f);
    const float inv2 = (n2 > 0.f) ? rsqrtf(n2) : 0.f;
    const float T20 = inv2 * (-d0 * inv0 - d1 * T10);
    const float T21 = inv2 * (-d1 * T11);
    const float T22 = inv2;

    const float e0 = g03 * inv0;
    const float e1 = T10 * g03 + T11 * g13;
    const float e2 = T20 * g03 + T21 * g13 + T22 * g23;
    const float n3 = fmaxf(g33 - e0 * e0 - e1 * e1 - e2 * e2, 0.f);
    const float inv3 = (n3 > 0.f) ? rsqrtf(n3) : 0.f;
    const float T30 = inv3 * (-e0 * inv0 - e1 * T10 - e2 * T20);
    const float T31 = inv3 * (-e1 * T11 - e2 * T21);
    const float T32 = inv3 * (-e2 * T22);
    const float T33 = inv3;

    // ---- outputs: basis_i = sum_j T_ij v_j (streaming stores) ----
    float4 o;
    o.x = inv0 * v0.x; o.y = inv0 * v0.y; o.z = inv0 * v0.z; o.w = inv0 * v0.w;
    __stcs((float4*)(ob + base), o);

    o.x = T10 * v0.x + T11 * v1.x; o.y = T10 * v0.y + T11 * v1.y;
    o.z = T10 * v0.z + T11 * v1.z; o.w = T10 * v0.w + T11 * v1.w;
    __stcs((float4*)(ob + base + MSTRIDE_B), o);

    o.x = T20 * v0.x + T21 * v1.x + T22 * v2.x;
    o.y = T20 * v0.y + T21 * v1.y + T22 * v2.y;
    o.z = T20 * v0.z + T21 * v1.z + T22 * v2.z;
    o.w = T20 * v0.w + T21 * v1.w + T22 * v2.w;
    __stcs((float4*)(ob + base + 2u * MSTRIDE_B), o);

    o.x = T30 * v0.x + T31 * v1.x + T32 * v2.x + T33 * v3.x;
    o.y = T30 * v0.y + T31 * v1.y + T32 * v2.y + T33 * v3.y;
    o.z = T30 * v0.z + T31 * v1.z + T32 * v2.z + T33 * v3.z;
    o.w = T30 * v0.w + T31 * v1.w + T32 * v2.w + T33 * v3.w;
    __stcs((float4*)(ob + base + 3u * MSTRIDE_B), o);
}

extern "C" void kernel_launch(void* const* d_in, const int* in_sizes, int n_in,
                              void* d_out, int out_size) {
    const float* x = (const float*)d_in[0];
    float* out = (float*)d_out;
    gram_schmidt_kernel<<<NPAIRS, NTHREADS>>>(x, out);
}